// round 1
// baseline (speedup 1.0000x reference)
#include <cuda_runtime.h>
#include <cuda_bf16.h>
#include <math.h>

#define N 8192
#define FIN 256
#define FOUT 64

// Scratch (module globals -- no allocation allowed in kernel_launch)
__device__ float g_Wh[(size_t)N * FOUT];
__device__ float g_fsrc[N];
__device__ float g_fdst[N];
__device__ float g_gmax;

// ---------------------------------------------------------------------------
// Kernel A: Wh = h @ W   (8192x256 @ 256x64)
// block = 256 threads: f = tid&63, group g = tid>>6 handles 8 rows.
// W staged through smem in two 128x64 tiles; h read as float4 (broadcast per group).
// ---------------------------------------------------------------------------
__global__ __launch_bounds__(256) void wh_kernel(const float* __restrict__ h,
                                                 const float* __restrict__ W) {
    __shared__ float Ws[128][FOUT];
    const int f = threadIdx.x & 63;
    const int g = threadIdx.x >> 6;            // 0..3
    const int row0 = blockIdx.x * 32 + g * 8;  // 32 rows per block

    float acc[8];
#pragma unroll
    for (int r = 0; r < 8; r++) acc[r] = 0.f;

    for (int t = 0; t < 2; t++) {
        __syncthreads();
        for (int idx = threadIdx.x; idx < 128 * FOUT; idx += 256)
            (&Ws[0][0])[idx] = W[t * 128 * FOUT + idx];
        __syncthreads();
#pragma unroll 1
        for (int r = 0; r < 8; r++) {
            const float4* hrow =
                (const float4*)(h + (size_t)(row0 + r) * FIN + t * 128);
            float a0 = acc[r];
#pragma unroll
            for (int k4 = 0; k4 < 32; k4++) {
                float4 hv = hrow[k4];
                a0 += hv.x * Ws[k4 * 4 + 0][f];
                a0 += hv.y * Ws[k4 * 4 + 1][f];
                a0 += hv.z * Ws[k4 * 4 + 2][f];
                a0 += hv.w * Ws[k4 * 4 + 3][f];
            }
            acc[r] = a0;
        }
    }
#pragma unroll
    for (int r = 0; r < 8; r++)
        g_Wh[(size_t)(row0 + r) * FOUT + f] = acc[r];
}

// ---------------------------------------------------------------------------
// Kernel B: f_src[i] = Wh[i,:] . a[0:64],  f_dst[i] = Wh[i,:] . a[64:128]
// ---------------------------------------------------------------------------
__global__ void fvec_kernel(const float* __restrict__ a) {
    const int i = blockIdx.x * blockDim.x + threadIdx.x;
    const float4* w4 = (const float4*)(g_Wh + (size_t)i * FOUT);
    const float4* a4 = (const float4*)a;
    float s = 0.f, d = 0.f;
#pragma unroll
    for (int q = 0; q < 16; q++) {
        float4 v = w4[q];
        float4 as_ = a4[q];
        float4 ad = a4[16 + q];
        s += v.x * as_.x + v.y * as_.y + v.z * as_.z + v.w * as_.w;
        d += v.x * ad.x + v.y * ad.y + v.z * ad.z + v.w * ad.w;
    }
    g_fsrc[i] = s;
    g_fdst[i] = d;
}

// ---------------------------------------------------------------------------
// Kernel C: gmax = max_j f_dst[j]
// ---------------------------------------------------------------------------
__global__ void gmax_kernel() {
    __shared__ float red[1024];
    float m = -1e30f;
    for (int i = threadIdx.x; i < N; i += 1024) m = fmaxf(m, g_fdst[i]);
    red[threadIdx.x] = m;
    __syncthreads();
    for (int s = 512; s > 0; s >>= 1) {
        if (threadIdx.x < s)
            red[threadIdx.x] = fmaxf(red[threadIdx.x], red[threadIdx.x + s]);
        __syncthreads();
    }
    if (threadIdx.x == 0) g_gmax = red[0];
}

// ---------------------------------------------------------------------------
// Kernel D: fused masked softmax + (attention @ Wh) + ELU.
// Block = 8 rows, 8 warps; each warp owns disjoint j-chunks of 32.
// Lane computes p for its own j (8 rows), then p is redistributed via shfl
// while lanes hold f = {2*lane, 2*lane+1} of Wh (coalesced float2 reads).
// Softmax uses fixed upper bound M_i = lrelu(f_src[i] + gmax): exp(s-M) <= 1,
// masked entries contribute exactly 0 -> identical to reference softmax.
// ---------------------------------------------------------------------------
__global__ __launch_bounds__(256) void gat_main_kernel(const int* __restrict__ adj,
                                                       float* __restrict__ out) {
    __shared__ float sfs[8], sM[8];
    __shared__ float sacc[8][8][64];  // [warp][row][f]
    __shared__ float sl[8][8];        // [warp][row]

    const int row0 = blockIdx.x * 8;
    const int lane = threadIdx.x & 31;
    const int warp = threadIdx.x >> 5;

    if (threadIdx.x < 8) {
        float fs = g_fsrc[row0 + threadIdx.x];
        float M = fs + g_gmax;
        M = M > 0.f ? M : 0.2f * M;  // leaky_relu, monotone -> valid upper bound
        sfs[threadIdx.x] = fs;
        sM[threadIdx.x] = M;
    }
    __syncthreads();

    float fsr[8], Mr[8];
#pragma unroll
    for (int r = 0; r < 8; r++) { fsr[r] = sfs[r]; Mr[r] = sM[r]; }

    float2 acc[8];
    float l[8];
#pragma unroll
    for (int r = 0; r < 8; r++) { acc[r] = make_float2(0.f, 0.f); l[r] = 0.f; }

    for (int c = 0; c < 32; c++) {
        const int jb = (c * 8 + warp) * 32;
        const int j = jb + lane;
        const float fd = g_fdst[j];

        float p[8];
#pragma unroll
        for (int r = 0; r < 8; r++) {
            int av = adj[(size_t)(row0 + r) * N + j];
            float s = fsr[r] + fd;
            s = s > 0.f ? s : 0.2f * s;
            p[r] = av ? __expf(s - Mr[r]) : 0.f;
            l[r] += p[r];
        }

        const float2* whb = ((const float2*)g_Wh) + (size_t)jb * 32 + lane;
#pragma unroll
        for (int jj = 0; jj < 32; jj++) {
            float2 w = whb[(size_t)jj * 32];
#pragma unroll
            for (int r = 0; r < 8; r++) {
                float pj = __shfl_sync(0xffffffffu, p[r], jj);
                acc[r].x += pj * w.x;
                acc[r].y += pj * w.y;
            }
        }
    }

    // reduce l across lanes of each warp
#pragma unroll
    for (int r = 0; r < 8; r++) {
#pragma unroll
        for (int off = 16; off > 0; off >>= 1)
            l[r] += __shfl_xor_sync(0xffffffffu, l[r], off);
    }
    if (lane == 0) {
#pragma unroll
        for (int r = 0; r < 8; r++) sl[warp][r] = l[r];
    }
#pragma unroll
    for (int r = 0; r < 8; r++) {
        sacc[warp][r][2 * lane] = acc[r].x;
        sacc[warp][r][2 * lane + 1] = acc[r].y;
    }
    __syncthreads();

    for (int idx = threadIdx.x; idx < 512; idx += 256) {
        const int r = idx >> 6, f = idx & 63;
        float s = 0.f, lt = 0.f;
#pragma unroll
        for (int w = 0; w < 8; w++) {
            s += sacc[w][r][f];
            lt += sl[w][r];
        }
        float o = s / lt;
        o = o > 0.f ? o : expm1f(o);  // ELU (alpha=1)
        out[(size_t)(row0 + r) * FOUT + f] = o;
    }
}

// ---------------------------------------------------------------------------
extern "C" void kernel_launch(void* const* d_in, const int* in_sizes, int n_in,
                              void* d_out, int out_size) {
    const float* h = (const float*)d_in[0];
    const int* adj = (const int*)d_in[1];
    const float* W = (const float*)d_in[2];
    const float* a = (const float*)d_in[3];
    float* out = (float*)d_out;

    wh_kernel<<<N / 32, 256>>>(h, W);
    fvec_kernel<<<N / 256, 256>>>(a);
    gmax_kernel<<<1, 1024>>>();
    gat_main_kernel<<<N / 8, 256>>>(adj, out);
}